// round 1
// baseline (speedup 1.0000x reference)
#include <cuda_runtime.h>
#include <cstdint>
#include <math.h>

// Problem constants: B=1, N=256, O=16, C=64, BASIS=32, WIDEN=4
// inputs: 0 x(1,256,16,64) 1 kernel_basis(1,256,256,16,32) 2 fiber_kernel_basis(16,16,32)
//         3 W_spatial(32,64) 4 W_rot(32,64) 5 conv_bias(64) 6 ln_scale(64) 7 ln_bias(64)
//         8 W1(64,256) 9 b1(256) 10 W2(256,64) 11 b2(64)   output: (1,256,16,64) f32

// ------------------------- scratch (static device globals; no allocs) -------------
__device__ float g_rk[16 * 16 * 64];          // rot kernel  (p,o,c)
__device__ float g_h1[2][256 * 16 * 64];      // k-split partials of spatial conv (m,o,c)

// ------------------------- small helpers ------------------------------------------
__device__ __forceinline__ uint32_t f2tf(float f) {
    uint32_t u;
    asm("cvt.rna.tf32.f32 %0, %1;" : "=r"(u) : "f"(f));
    return u;
}

__device__ __forceinline__ void mma8(float* acc,
                                     uint32_t a0, uint32_t a1, uint32_t a2, uint32_t a3,
                                     uint32_t b0, uint32_t b1) {
    asm volatile(
        "mma.sync.aligned.m16n8k8.row.col.f32.tf32.tf32.f32 "
        "{%0,%1,%2,%3}, {%4,%5,%6,%7}, {%8,%9}, {%0,%1,%2,%3};"
        : "+f"(acc[0]), "+f"(acc[1]), "+f"(acc[2]), "+f"(acc[3])
        : "r"(a0), "r"(a1), "r"(a2), "r"(a3), "r"(b0), "r"(b1));
}

__device__ __forceinline__ void cpa16(void* smemdst, const void* gsrc) {
    uint32_t sa = (uint32_t)__cvta_generic_to_shared(smemdst);
    asm volatile("cp.async.cg.shared.global [%0], [%1], 16;" :: "r"(sa), "l"(gsrc));
}

__device__ __forceinline__ float gelu_f(float z) {
    float t = 0.7978845608028654f * (z + 0.044715f * z * z * z);
    return 0.5f * z * (1.0f + tanhf(t));
}

// ------------------------- kernel 1: rot kernel projection ------------------------
// rk[p,o,c] = sum_s fkb[p,o,s] * Wr[s,c]
__global__ void rotk_kernel(const float* __restrict__ fkb, const float* __restrict__ Wr) {
    int po = blockIdx.x;    // 0..255 = p*16+o
    int c  = threadIdx.x;   // 0..63
    float acc = 0.f;
#pragma unroll
    for (int s = 0; s < 32; s++)
        acc += fkb[po * 32 + s] * Wr[s * 64 + c];
    g_rk[po * 64 + c] = acc;
}

// ------------------------- kernel 2: big spatial conv GEMM ------------------------
// For fixed o:  H[m, c] = sum_{k=(n,s)} kb[m,n,o,s] * ( x[n,o,c] * Ws[s,c] )
// grid: (8 m-tiles of 32, 16 o, 2 k-splits). 256 threads = 8 warps.
// Each warp owns m16 x c16 (two n8 mma tiles). K-tile per iter = 64 (2 n-points).
__global__ __launch_bounds__(256) void conv_kernel(const float* __restrict__ x,
                                                   const float* __restrict__ kb,
                                                   const float* __restrict__ Wsp) {
    __shared__ __align__(16) float    sA[2][32][68];   // kb tile, fp32 (cvt at frag load)
    __shared__ __align__(16) uint32_t sB[64][72];      // tf32(x*Ws) tile
    __shared__ __align__(16) float    sX[2][2][64];    // two x rows per iter

    const int tid = threadIdx.x;
    const int m0  = blockIdx.x * 32;
    const int o   = blockIdx.y;
    const int ks  = blockIdx.z;

    // W_spatial values this thread needs for B-tile construction (fixed mapping)
    float regWs[16];
    {
        int r  = tid & 31;
        int c0 = (tid >> 6) * 16;
#pragma unroll
        for (int j = 0; j < 16; j++) regWs[j] = Wsp[r * 64 + c0 + j];
    }

    const int w = tid >> 5, lane = tid & 31;
    const int mh = (w >> 2) * 16;       // m offset within the 32-row tile
    const int cg = (w & 3) * 16;        // c offset
    const int g = lane >> 2, tq = lane & 3;
    float acc0[4] = {0.f, 0.f, 0.f, 0.f};
    float acc1[4] = {0.f, 0.f, 0.f, 0.f};

    auto prefetch = [&](int iter, int buf) {
        int n0 = ks * 128 + iter * 2;
        // A tile: 32 rows x 64 floats = 512 x 16B chunks
#pragma unroll
        for (int h = 0; h < 2; h++) {
            int q   = tid + h * 256;
            int row = q >> 4, j = q & 15;
            const float* src = kb + (size_t)(m0 + row) * 131072
                                  + (size_t)(n0 + (j >> 3)) * 512
                                  + o * 32 + (j & 7) * 4;
            cpa16(&sA[buf][row][j * 4], src);
        }
        // x rows: 2 x 64 floats = 32 x 16B chunks
        if (tid < 32) {
            int ni = tid >> 4, jj = tid & 15;
            const float* src = x + (size_t)(n0 + ni) * 1024 + o * 64 + jj * 4;
            cpa16(&sX[buf][ni][jj * 4], src);
        }
    };

    prefetch(0, 0);
    asm volatile("cp.async.commit_group;" ::: "memory");

    const int bkk = tid & 63;           // B-tile k row this thread builds
    const int bc0 = (tid >> 6) * 16;    // B-tile c range

    for (int i = 0; i < 64; i++) {
        int cur = i & 1;
        asm volatile("cp.async.wait_group 0;" ::: "memory");
        __syncthreads();                 // buf[cur] ready; prior iter's mma reads done
        if (i + 1 < 64) {
            prefetch(i + 1, cur ^ 1);
            asm volatile("cp.async.commit_group;" ::: "memory");
        }
        // Build B tile: sB[kk][c] = tf32( x[n0 + kk/32][c] * Ws[kk%32][c] )
        {
            const float* xr = &sX[cur][bkk >> 5][bc0];
            uint32_t*    bd = &sB[bkk][bc0];
#pragma unroll
            for (int j = 0; j < 16; j += 4) {
                float4 xv = *(const float4*)(xr + j);
                uint4 ov;
                ov.x = f2tf(xv.x * regWs[j + 0]);
                ov.y = f2tf(xv.y * regWs[j + 1]);
                ov.z = f2tf(xv.z * regWs[j + 2]);
                ov.w = f2tf(xv.w * regWs[j + 3]);
                *(uint4*)(bd + j) = ov;
            }
        }
        __syncthreads();
        // 8 k-steps of m16n8k8 tf32 mma
#pragma unroll
        for (int step = 0; step < 8; step++) {
            int k0 = step * 8;
            uint32_t a0 = f2tf(sA[cur][mh + g    ][k0 + tq    ]);
            uint32_t a1 = f2tf(sA[cur][mh + g + 8][k0 + tq    ]);
            uint32_t a2 = f2tf(sA[cur][mh + g    ][k0 + tq + 4]);
            uint32_t a3 = f2tf(sA[cur][mh + g + 8][k0 + tq + 4]);
            uint32_t b0 = sB[k0 + tq    ][cg + g];
            uint32_t b1 = sB[k0 + tq + 4][cg + g];
            mma8(acc0, a0, a1, a2, a3, b0, b1);
            b0 = sB[k0 + tq    ][cg + 8 + g];
            b1 = sB[k0 + tq + 4][cg + 8 + g];
            mma8(acc1, a0, a1, a2, a3, b0, b1);
        }
    }

    // Epilogue: write partials. mma C layout: c0=(g, 2*tq), c1=+1, c2=(g+8, 2*tq), c3=+1
    float* outp = g_h1[ks];
    int r0   = m0 + mh + g;
    int base = (r0 * 16 + o) * 64 + cg + tq * 2;
    outp[base + 0] = acc0[0];
    outp[base + 1] = acc0[1];
    outp[base + 8] = acc1[0];
    outp[base + 9] = acc1[1];
    base += 8 * 16 * 64;  // row + 8
    outp[base + 0] = acc0[2];
    outp[base + 1] = acc0[3];
    outp[base + 8] = acc1[2];
    outp[base + 9] = acc1[3];
}

// ------------------------- kernel 3: fiber conv + LN + MLP + residual -------------
// 128 blocks, 2 m-values each (32 rows of 64 channels). 256 threads.
__global__ __launch_bounds__(256) void tail_kernel(const float* __restrict__ x,
                                                   const float* __restrict__ cb,
                                                   const float* __restrict__ lns,
                                                   const float* __restrict__ lnb,
                                                   const float* __restrict__ W1,
                                                   const float* __restrict__ b1,
                                                   const float* __restrict__ W2,
                                                   const float* __restrict__ b2,
                                                   float* __restrict__ out) {
    __shared__ __align__(16) float sm[2048 + 32 * 260];
    float* v  = sm;          // post-LN activations [32][64]
    float* u  = sm + 2048;   // MLP hidden [32][260 padded]
    float* hs = u;           // stage-1 alias: conv partial sums [2][16][64]

    const int tid   = threadIdx.x;
    const int m0    = blockIdx.x * 2;
    const int gbase = m0 * 1024;

    // 1) sum k-split partials for our 2 m-values
    for (int i = tid; i < 2048; i += 256)
        hs[i] = g_h1[0][gbase + i] + g_h1[1][gbase + i];
    __syncthreads();

    // 2) fiber conv over o + conv_bias, then LayerNorm over c
    {
        int row = tid >> 3;             // 0..31 = mi*16 + p
        int mi = row >> 4, pp = row & 15;
        int c0 = (tid & 7) * 8;
        float hv[8];
#pragma unroll
        for (int j = 0; j < 8; j++) hv[j] = __ldg(&cb[c0 + j]);
#pragma unroll
        for (int oo = 0; oo < 16; oo++) {
            const float* hp = &hs[(mi * 16 + oo) * 64 + c0];
            const float* rp = &g_rk[(pp * 16 + oo) * 64 + c0];
            float4 h0 = *(const float4*)hp;
            float4 h1 = *(const float4*)(hp + 4);
            float4 q0 = __ldg((const float4*)rp);
            float4 q1 = __ldg((const float4*)(rp + 4));
            hv[0] += h0.x * q0.x; hv[1] += h0.y * q0.y;
            hv[2] += h0.z * q0.z; hv[3] += h0.w * q0.w;
            hv[4] += h1.x * q1.x; hv[5] += h1.y * q1.y;
            hv[6] += h1.z * q1.z; hv[7] += h1.w * q1.w;
        }
        // LayerNorm: 8 lanes per row
        float s = 0.f;
#pragma unroll
        for (int j = 0; j < 8; j++) s += hv[j];
        s += __shfl_xor_sync(0xffffffffu, s, 1);
        s += __shfl_xor_sync(0xffffffffu, s, 2);
        s += __shfl_xor_sync(0xffffffffu, s, 4);
        float mu = s * (1.f / 64.f);
        float d[8], ss = 0.f;
#pragma unroll
        for (int j = 0; j < 8; j++) { d[j] = hv[j] - mu; ss += d[j] * d[j]; }
        ss += __shfl_xor_sync(0xffffffffu, ss, 1);
        ss += __shfl_xor_sync(0xffffffffu, ss, 2);
        ss += __shfl_xor_sync(0xffffffffu, ss, 4);
        float rs = rsqrtf(ss * (1.f / 64.f) + 1e-6f);
        float4 o0, o1;
        o0.x = d[0] * rs * __ldg(&lns[c0 + 0]) + __ldg(&lnb[c0 + 0]);
        o0.y = d[1] * rs * __ldg(&lns[c0 + 1]) + __ldg(&lnb[c0 + 1]);
        o0.z = d[2] * rs * __ldg(&lns[c0 + 2]) + __ldg(&lnb[c0 + 2]);
        o0.w = d[3] * rs * __ldg(&lns[c0 + 3]) + __ldg(&lnb[c0 + 3]);
        o1.x = d[4] * rs * __ldg(&lns[c0 + 4]) + __ldg(&lnb[c0 + 4]);
        o1.y = d[5] * rs * __ldg(&lns[c0 + 5]) + __ldg(&lnb[c0 + 5]);
        o1.z = d[6] * rs * __ldg(&lns[c0 + 6]) + __ldg(&lnb[c0 + 6]);
        o1.w = d[7] * rs * __ldg(&lns[c0 + 7]) + __ldg(&lnb[c0 + 7]);
        *(float4*)&v[row * 64 + c0]     = o0;
        *(float4*)&v[row * 64 + c0 + 4] = o1;
    }
    __syncthreads();

    // 3) GEMM1 (64 -> 256) + gelu   (writes u; hs is dead)
    {
        int r0 = (tid >> 5) * 4;
        int j0 = (tid & 31) * 8;
        float acc[4][8];
#pragma unroll
        for (int r = 0; r < 4; r++)
#pragma unroll
            for (int j = 0; j < 8; j++) acc[r][j] = 0.f;
        for (int c = 0; c < 64; c++) {
            float4 wa = __ldg((const float4*)&W1[c * 256 + j0]);
            float4 wb = __ldg((const float4*)&W1[c * 256 + j0 + 4]);
            float vv[4];
#pragma unroll
            for (int r = 0; r < 4; r++) vv[r] = v[(r0 + r) * 64 + c];
#pragma unroll
            for (int r = 0; r < 4; r++) {
                acc[r][0] += vv[r] * wa.x; acc[r][1] += vv[r] * wa.y;
                acc[r][2] += vv[r] * wa.z; acc[r][3] += vv[r] * wa.w;
                acc[r][4] += vv[r] * wb.x; acc[r][5] += vv[r] * wb.y;
                acc[r][6] += vv[r] * wb.z; acc[r][7] += vv[r] * wb.w;
            }
        }
#pragma unroll
        for (int r = 0; r < 4; r++) {
            float4 s0, s1;
            s0.x = gelu_f(acc[r][0] + __ldg(&b1[j0 + 0]));
            s0.y = gelu_f(acc[r][1] + __ldg(&b1[j0 + 1]));
            s0.z = gelu_f(acc[r][2] + __ldg(&b1[j0 + 2]));
            s0.w = gelu_f(acc[r][3] + __ldg(&b1[j0 + 3]));
            s1.x = gelu_f(acc[r][4] + __ldg(&b1[j0 + 4]));
            s1.y = gelu_f(acc[r][5] + __ldg(&b1[j0 + 5]));
            s1.z = gelu_f(acc[r][6] + __ldg(&b1[j0 + 6]));
            s1.w = gelu_f(acc[r][7] + __ldg(&b1[j0 + 7]));
            *(float4*)&u[(r0 + r) * 260 + j0]     = s0;
            *(float4*)&u[(r0 + r) * 260 + j0 + 4] = s1;
        }
    }
    __syncthreads();

    // 4) GEMM2 (256 -> 64) + bias + residual
    {
        int rr = (tid >> 4) * 2;
        int cc = (tid & 15) * 4;
        float4 a0 = {0.f, 0.f, 0.f, 0.f};
        float4 a1 = {0.f, 0.f, 0.f, 0.f};
        for (int jj = 0; jj < 256; jj++) {
            float u0 = u[rr * 260 + jj];
            float u1 = u[(rr + 1) * 260 + jj];
            float4 wv = __ldg((const float4*)&W2[jj * 64 + cc]);
            a0.x += u0 * wv.x; a0.y += u0 * wv.y; a0.z += u0 * wv.z; a0.w += u0 * wv.w;
            a1.x += u1 * wv.x; a1.y += u1 * wv.y; a1.z += u1 * wv.z; a1.w += u1 * wv.w;
        }
        float4 bb = __ldg((const float4*)&b2[cc]);
        int grow = m0 * 16 + rr;
        float4 xr0 = __ldg((const float4*)&x[grow * 64 + cc]);
        float4 xr1 = __ldg((const float4*)&x[(grow + 1) * 64 + cc]);
        float4 r0v, r1v;
        r0v.x = a0.x + bb.x + xr0.x; r0v.y = a0.y + bb.y + xr0.y;
        r0v.z = a0.z + bb.z + xr0.z; r0v.w = a0.w + bb.w + xr0.w;
        r1v.x = a1.x + bb.x + xr1.x; r1v.y = a1.y + bb.y + xr1.y;
        r1v.z = a1.z + bb.z + xr1.z; r1v.w = a1.w + bb.w + xr1.w;
        *(float4*)&out[grow * 64 + cc]       = r0v;
        *(float4*)&out[(grow + 1) * 64 + cc] = r1v;
    }
}

// ------------------------- launch ------------------------------------------------
extern "C" void kernel_launch(void* const* d_in, const int* in_sizes, int n_in,
                              void* d_out, int out_size) {
    const float* x   = (const float*)d_in[0];
    const float* kb  = (const float*)d_in[1];
    const float* fkb = (const float*)d_in[2];
    const float* Wsp = (const float*)d_in[3];
    const float* Wr  = (const float*)d_in[4];
    const float* cb  = (const float*)d_in[5];
    const float* lns = (const float*)d_in[6];
    const float* lnb = (const float*)d_in[7];
    const float* W1  = (const float*)d_in[8];
    const float* b1  = (const float*)d_in[9];
    const float* W2  = (const float*)d_in[10];
    const float* b2  = (const float*)d_in[11];
    float* out = (float*)d_out;

    rotk_kernel<<<256, 64>>>(fkb, Wr);
    conv_kernel<<<dim3(8, 16, 2), 256>>>(x, kb, Wsp);
    tail_kernel<<<128, 256>>>(x, cb, lns, lnb, W1, b1, W2, b2, out);
}

// round 4
// speedup vs baseline: 1.0913x; 1.0913x over previous
#include <cuda_runtime.h>
#include <cstdint>
#include <math.h>

// Problem: B=1, N=256, O=16, C=64, BASIS=32, WIDEN=4
// h[m,o,c] = sum_{n,s} kb[m,n,o,s] * x[n,o,c] * Ws[s,c]
// then fiber conv over o with rk = fkb@Wr, +bias, LN, MLP(gelu), +x residual.
//
// conv: legacy mma.sync m16n8k8 tf32. Warp tile m16 x n64. A fragments LDG'd
// directly from gmem (k-permuted so each lane's pair is one LDG.64). B built
// on the fly in SMEM (transposed [c][k], stride 40 words = conflict-free).

#define KS 8
#define NTILES 32
#define BSTRIDE 40

__device__ float g_rk[16 * 16 * 64];
__device__ float g_h1[KS][256 * 16 * 64];

// ------------------------- helpers ------------------------------------------------
__device__ __forceinline__ uint32_t f2tf(float f) {
    uint32_t u;
    asm("cvt.rna.tf32.f32 %0, %1;" : "=r"(u) : "f"(f));
    return u;
}

__device__ __forceinline__ void mma8(float* acc,
                                     uint32_t a0, uint32_t a1, uint32_t a2, uint32_t a3,
                                     uint32_t b0, uint32_t b1) {
    asm volatile(
        "mma.sync.aligned.m16n8k8.row.col.f32.tf32.tf32.f32 "
        "{%0,%1,%2,%3}, {%4,%5,%6,%7}, {%8,%9}, {%0,%1,%2,%3};"
        : "+f"(acc[0]), "+f"(acc[1]), "+f"(acc[2]), "+f"(acc[3])
        : "r"(a0), "r"(a1), "r"(a2), "r"(a3), "r"(b0), "r"(b1));
}

__device__ __forceinline__ float gelu_f(float z) {
    float t = 0.7978845608028654f * (z + 0.044715f * z * z * z);
    return 0.5f * z * (1.0f + tanhf(t));
}

// ------------------------- kernel 1: conv + folded rotk ---------------------------
// grid (2 m-tiles, 16 o, 9): z=0..7 k-splits (32 n-points each); z==8 does rotk.
__global__ __launch_bounds__(256, 2) void conv_kernel(const float* __restrict__ x,
                                                      const float* __restrict__ kb,
                                                      const float* __restrict__ Wsp,
                                                      const float* __restrict__ fkb,
                                                      const float* __restrict__ Wr) {
    if (blockIdx.z == 8) {
        // rot kernel projection: rk[po][c] = sum_s fkb[po*32+s] * Wr[s*64+c]
        int id = blockIdx.x * 16 + blockIdx.y;   // 0..31
        for (int idx = threadIdx.x; idx < 512; idx += 256) {
            int po = id * 8 + (idx >> 6), c = idx & 63;
            float acc = 0.f;
#pragma unroll
            for (int s = 0; s < 32; s++) acc += fkb[po * 32 + s] * Wr[s * 64 + c];
            g_rk[po * 64 + c] = acc;
        }
        return;
    }

    __shared__ __align__(16) uint32_t sBT[2][64 * BSTRIDE];  // tf32(x*Ws), [c][k] transposed
    __shared__ __align__(16) float    sx[32 * 64];           // x rows for our 32 n-points

    const int tid  = threadIdx.x;
    const int w    = tid >> 5;
    const int lane = tid & 31;
    const int g    = lane >> 2;      // row-in-8
    const int tq   = lane & 3;       // thread-in-group
    const int m0   = blockIdx.x * 128;
    const int o    = blockIdx.y;
    const int ks   = blockIdx.z;
    const int n0   = ks * 32;

    // --- preload x rows (n0..n0+31, orientation o) into smem ---
    for (int i4 = tid; i4 < 512; i4 += 256) {
        int n_i = i4 >> 4, c4 = i4 & 15;
        ((float4*)sx)[i4] = __ldg((const float4*)(x + (size_t)(n0 + n_i) * 1024 + o * 64 + c4 * 4));
    }

    // --- B-build assignment: thread -> (c = tid/4, k-range q0 = (tid%4)*8) ---
    const int bc = tid >> 2, bq0 = (tid & 3) * 8;
    float ws[8];
#pragma unroll
    for (int i = 0; i < 8; i++) ws[i] = __ldg(&Wsp[(bq0 + i) * 64 + bc]);

    __syncthreads();

    // --- A base pointers (k-permuted fragment gather: one LDG.64 per (j,row)) ---
    // mrow = m0 + w*16 + g ; lane reads cols 8j+2tq, 8j+2tq+1 at rows mrow, mrow+8
    const float* pa0 = kb + (size_t)(m0 + w * 16 + g) * 131072 + o * 32 + 2 * tq;
    const float* pa1 = pa0 + (size_t)8 * 131072;

    float2 aA[2][8];   // double-buffered A fragments (raw fp32; cvt at use)
    auto loadA = [&](float2* dst, int t) {
        const size_t noff = (size_t)(n0 + t) * 512;
#pragma unroll
        for (int j = 0; j < 4; j++) {
            dst[2 * j]     = __ldg((const float2*)(pa0 + noff + 8 * j));
            dst[2 * j + 1] = __ldg((const float2*)(pa1 + noff + 8 * j));
        }
    };

    auto buildB = [&](int buf, int t) {
        float xv = sx[t * 64 + bc];
        uint32_t* dst = &sBT[buf][bc * BSTRIDE + bq0];
        uint4 u0, u1;
        u0.x = f2tf(xv * ws[0]); u0.y = f2tf(xv * ws[1]);
        u0.z = f2tf(xv * ws[2]); u0.w = f2tf(xv * ws[3]);
        u1.x = f2tf(xv * ws[4]); u1.y = f2tf(xv * ws[5]);
        u1.z = f2tf(xv * ws[6]); u1.w = f2tf(xv * ws[7]);
        *(uint4*)dst       = u0;
        *(uint4*)(dst + 4) = u1;
    };

    float acc[8][4];
#pragma unroll
    for (int G = 0; G < 8; G++)
#pragma unroll
        for (int i = 0; i < 4; i++) acc[G][i] = 0.f;

    buildB(0, 0);
    loadA(aA[0], 0);
    __syncthreads();

    for (int t = 0; t < NTILES; t++) {
        const int cur = t & 1;
        if (t + 1 < NTILES) {
            loadA(aA[cur ^ 1], t + 1);      // LDGs for next tile in flight
            buildB(cur ^ 1, t + 1);         // build next B tile (other buffer)
        }
        // consume tile t
        const uint32_t* BT = sBT[cur];
#pragma unroll
        for (int j = 0; j < 4; j++) {
            uint32_t a0 = f2tf(aA[cur][2 * j].x);
            uint32_t a2 = f2tf(aA[cur][2 * j].y);
            uint32_t a1 = f2tf(aA[cur][2 * j + 1].x);
            uint32_t a3 = f2tf(aA[cur][2 * j + 1].y);
            const int ko = 8 * j + 2 * tq;
#pragma unroll
            for (int G = 0; G < 8; G++) {
                uint2 b = *(const uint2*)&BT[(G * 8 + g) * BSTRIDE + ko];
                mma8(acc[G], a0, a1, a2, a3, b.x, b.y);
            }
        }
        __syncthreads();   // all reads of buf `cur` done; next build may overwrite
    }

    // --- epilogue: write partials. D frag: c0=(g,2tq) c1=(g,2tq+1) c2=(g+8,..) ---
    {
        float* dst0 = g_h1[ks] + ((size_t)(m0 + w * 16 + g) * 16 + o) * 64 + 2 * tq;
        float* dst1 = dst0 + (size_t)8 * 16 * 64;
#pragma unroll
        for (int G = 0; G < 8; G++) {
            float2 v0 = {acc[G][0], acc[G][1]};
            float2 v1 = {acc[G][2], acc[G][3]};
            *(float2*)(dst0 + G * 8) = v0;
            *(float2*)(dst1 + G * 8) = v1;
        }
    }
}

// ------------------------- kernel 2: fiber conv + LN + MLP + residual -------------
__global__ __launch_bounds__(256) void tail_kernel(const float* __restrict__ x,
                                                   const float* __restrict__ cb,
                                                   const float* __restrict__ lns,
                                                   const float* __restrict__ lnb,
                                                   const float* __restrict__ W1,
                                                   const float* __restrict__ b1,
                                                   const float* __restrict__ W2,
                                                   const float* __restrict__ b2,
                                                   float* __restrict__ out) {
    __shared__ __align__(16) float sm[2048 + 32 * 260];
    float* v  = sm;          // post-LN activations [32][64]
    float* u  = sm + 2048;   // MLP hidden [32][260 padded]
    float* hs = u;           // stage-1 alias: conv sums [2][16][64]

    const int tid = threadIdx.x;
    const int m0  = blockIdx.x * 2;

    // 1) sum KS k-split partials
    {
        int gb4 = blockIdx.x * 512;  // float4 index of (m0*1024)
        for (int i = tid; i < 512; i += 256) {
            float4 a = ((const float4*)g_h1[0])[gb4 + i];
#pragma unroll
            for (int q = 1; q < KS; q++) {
                float4 b = ((const float4*)g_h1[q])[gb4 + i];
                a.x += b.x; a.y += b.y; a.z += b.z; a.w += b.w;
            }
            ((float4*)hs)[i] = a;
        }
    }
    __syncthreads();

    // 2) fiber conv over o + conv_bias, then LayerNorm over c
    {
        int row = tid >> 3;             // 0..31 = mi*16 + p
        int mi = row >> 4, pp = row & 15;
        int c0 = (tid & 7) * 8;
        float hv[8];
#pragma unroll
        for (int j = 0; j < 8; j++) hv[j] = __ldg(&cb[c0 + j]);
#pragma unroll
        for (int oo = 0; oo < 16; oo++) {
            const float* hp = &hs[(mi * 16 + oo) * 64 + c0];
            const float* rp = &g_rk[(pp * 16 + oo) * 64 + c0];
            float4 h0 = *(const float4*)hp;
            float4 h1 = *(const float4*)(hp + 4);
            float4 q0 = __ldg((const float4*)rp);
            float4 q1 = __ldg((const float4*)(rp + 4));
            hv[0] += h0.x * q0.x; hv[1] += h0.y * q0.y;
            hv[2] += h0.z * q0.z; hv[3] += h0.w * q0.w;
            hv[4] += h1.x * q1.x; hv[5] += h1.y * q1.y;
            hv[6] += h1.z * q1.z; hv[7] += h1.w * q1.w;
        }
        float s = 0.f;
#pragma unroll
        for (int j = 0; j < 8; j++) s += hv[j];
        s += __shfl_xor_sync(0xffffffffu, s, 1);
        s += __shfl_xor_sync(0xffffffffu, s, 2);
        s += __shfl_xor_sync(0xffffffffu, s, 4);
        float mu = s * (1.f / 64.f);
        float d[8], ss = 0.f;
#pragma unroll
        for (int j = 0; j < 8; j++) { d[j] = hv[j] - mu; ss += d[j] * d[j]; }
        ss += __shfl_xor_sync(0xffffffffu, ss, 1);
        ss += __shfl_xor_sync(0xffffffffu, ss, 2);
        ss += __shfl_xor_sync(0xffffffffu, ss, 4);
        float rs = rsqrtf(ss * (1.f / 64.f) + 1e-6f);
        float4 o0, o1;
        o0.x = d[0] * rs * __ldg(&lns[c0 + 0]) + __ldg(&lnb[c0 + 0]);
        o0.y = d[1] * rs * __ldg(&lns[c0 + 1]) + __ldg(&lnb[c0 + 1]);
        o0.z = d[2] * rs * __ldg(&lns[c0 + 2]) + __ldg(&lnb[c0 + 2]);
        o0.w = d[3] * rs * __ldg(&lns[c0 + 3]) + __ldg(&lnb[c0 + 3]);
        o1.x = d[4] * rs * __ldg(&lns[c0 + 4]) + __ldg(&lnb[c0 + 4]);
        o1.y = d[5] * rs * __ldg(&lns[c0 + 5]) + __ldg(&lnb[c0 + 5]);
        o1.z = d[6] * rs * __ldg(&lns[c0 + 6]) + __ldg(&lnb[c0 + 6]);
        o1.w = d[7] * rs * __ldg(&lns[c0 + 7]) + __ldg(&lnb[c0 + 7]);
        *(float4*)&v[row * 64 + c0]     = o0;
        *(float4*)&v[row * 64 + c0 + 4] = o1;
    }
    __syncthreads();

    // 3) GEMM1 (64 -> 256) + gelu   (writes u; hs is dead)
    {
        int r0 = (tid >> 5) * 4;
        int j0 = (tid & 31) * 8;
        float acc[4][8];
#pragma unroll
        for (int r = 0; r < 4; r++)
#pragma unroll
            for (int j = 0; j < 8; j++) acc[r][j] = 0.f;
        for (int c = 0; c < 64; c++) {
            float4 wa = __ldg((const float4*)&W1[c * 256 + j0]);
            float4 wb = __ldg((const float4*)&W1[c * 256 + j0 + 4]);
            float vv[4];
#pragma unroll
            for (int r = 0; r < 4; r++) vv[r] = v[(r0 + r) * 64 + c];
#pragma unroll
            for (int r = 0; r < 4; r++) {
                acc[r][0] += vv[r] * wa.x; acc[r][1] += vv[r] * wa.y;
                acc[r][2] += vv[r] * wa.z; acc[r][3] += vv[r] * wa.w;
                acc[r][4] += vv[r] * wb.x; acc[r][5] += vv[r] * wb.y;
                acc[r][6] += vv[r] * wb.z; acc[r][7] += vv[r] * wb.w;
            }
        }
#pragma unroll
        for (int r = 0; r < 4; r++) {
            float4 s0, s1;
            s0.x = gelu_f(acc[r][0] + __ldg(&b1[j0 + 0]));
            s0.y = gelu_f(acc[r][1] + __ldg(&b1[j0 + 1]));
            s0.z = gelu_f(acc[r][2] + __ldg(&b1[j0 + 2]));
            s0.w = gelu_f(acc[r][3] + __ldg(&b1[j0 + 3]));
            s1.x = gelu_f(acc[r][4] + __ldg(&b1[j0 + 4]));
            s1.y = gelu_f(acc[r][5] + __ldg(&b1[j0 + 5]));
            s1.z = gelu_f(acc[r][6] + __ldg(&b1[j0 + 6]));
            s1.w = gelu_f(acc[r][7] + __ldg(&b1[j0 + 7]));
            *(float4*)&u[(r0 + r) * 260 + j0]     = s0;
            *(float4*)&u[(r0 + r) * 260 + j0 + 4] = s1;
        }
    }
    __syncthreads();

    // 4) GEMM2 (256 -> 64) + bias + residual
    {
        int rr = (tid >> 4) * 2;
        int cc = (tid & 15) * 4;
        float4 a0 = {0.f, 0.f, 0.f, 0.f};
        float4 a1 = {0.f, 0.f, 0.f, 0.f};
        for (int jj = 0; jj < 256; jj++) {
            float u0 = u[rr * 260 + jj];
            float u1 = u[(rr + 1) * 260 + jj];
            float4 wv = __ldg((const float4*)&W2[jj * 64 + cc]);
            a0.x += u0 * wv.x; a0.y += u0 * wv.y; a0.z += u0 * wv.z; a0.w += u0 * wv.w;
            a1.x += u1 * wv.x; a1.y += u1 * wv.y; a1.z += u1 * wv.z; a1.w += u1 * wv.w;
        }
        float4 bb = __ldg((const float4*)&b2[cc]);
        int grow = m0 * 16 + rr;
        float4 xr0 = __ldg((const float4*)&x[grow * 64 + cc]);
        float4 xr1 = __ldg((const float4*)&x[(grow + 1) * 64 + cc]);
        float4 r0v, r1v;
        r0v.x = a0.x + bb.x + xr0.x; r0v.y = a0.y + bb.y + xr0.y;
        r0v.z = a0.z + bb.z + xr0.z; r0v.w = a0.w + bb.w + xr0.w;
        r1v.x = a1.x + bb.x + xr1.x; r1v.y = a1.y + bb.y + xr1.y;
        r1v.z = a1.z + bb.z + xr1.z; r1v.w = a1.w + bb.w + xr1.w;
        *(float4*)&out[grow * 64 + cc]       = r0v;
        *(float4*)&out[(grow + 1) * 64 + cc] = r1v;
    }
}

// ------------------------- launch ------------------------------------------------
extern "C" void kernel_launch(void* const* d_in, const int* in_sizes, int n_in,
                              void* d_out, int out_size) {
    const float* x   = (const float*)d_in[0];
    const float* kb  = (const float*)d_in[1];
    const float* fkb = (const float*)d_in[2];
    const float* Wsp = (const float*)d_in[3];
    const float* Wr  = (const float*)d_in[4];
    const float* cb  = (const float*)d_in[5];
    const float* lns = (const float*)d_in[6];
    const float* lnb = (const float*)d_in[7];
    const float* W1  = (const float*)d_in[8];
    const float* b1  = (const float*)d_in[9];
    const float* W2  = (const float*)d_in[10];
    const float* b2  = (const float*)d_in[11];
    float* out = (float*)d_out;

    conv_kernel<<<dim3(2, 16, 9), 256>>>(x, kb, Wsp, fkb, Wr);
    tail_kernel<<<128, 256>>>(x, cb, lns, lnb, W1, b1, W2, b2, out);
}

// round 5
// speedup vs baseline: 1.5126x; 1.3862x over previous
#include <cuda_runtime.h>
#include <cstdint>
#include <math.h>

// Problem: B=1, N=256, O=16, C=64, BASIS=32, WIDEN=4
// h[m,o,c] = sum_{n,s} kb[m,n,o,s] * x[n,o,c] * Ws[s,c]   (tf32 mma.sync)
// then fiber conv over o with rk = fkb@Wr, +bias, LN, MLP(gelu), +x residual.

#define KS 8
#define NT 32
#define AST 40                    // A smem row stride (words): conflict-free LDS.64
#define BST 40                    // B smem row stride (words)
#define A_STAGE (128 * AST * 4)   // 20480 B per A stage
#define B_BUF   (64 * BST * 4)    // 10240 B per B buffer
#define A_OFF   0
#define B_OFF   (4 * A_STAGE)     // 81920
#define SX_OFF  (B_OFF + 2 * B_BUF)  // 102400
#define SMEMSZ  (SX_OFF + 32 * 64 * 4)  // 110592

__device__ float g_rk[16 * 16 * 64];
__device__ float g_h1[KS][256 * 16 * 64];
__device__ float g_v[256 * 16 * 64];

// ------------------------- helpers ------------------------------------------------
__device__ __forceinline__ uint32_t f2tf(float f) {
    uint32_t u;
    asm("cvt.rna.tf32.f32 %0, %1;" : "=r"(u) : "f"(f));
    return u;
}
__device__ __forceinline__ uint32_t smem_u32(const void* p) {
    uint32_t a;
    asm("{ .reg .u64 t; cvta.to.shared.u64 t, %1; cvt.u32.u64 %0, t; }" : "=r"(a) : "l"(p));
    return a;
}
__device__ __forceinline__ void cpa16(uint32_t smemdst, const void* gsrc) {
    asm volatile("cp.async.cg.shared.global [%0], [%1], 16;" :: "r"(smemdst), "l"(gsrc));
}
__device__ __forceinline__ void mma8(float* acc,
                                     uint32_t a0, uint32_t a1, uint32_t a2, uint32_t a3,
                                     uint32_t b0, uint32_t b1) {
    asm volatile(
        "mma.sync.aligned.m16n8k8.row.col.f32.tf32.tf32.f32 "
        "{%0,%1,%2,%3}, {%4,%5,%6,%7}, {%8,%9}, {%0,%1,%2,%3};"
        : "+f"(acc[0]), "+f"(acc[1]), "+f"(acc[2]), "+f"(acc[3])
        : "r"(a0), "r"(a1), "r"(a2), "r"(a3), "r"(b0), "r"(b1));
}
__device__ __forceinline__ float gelu_f(float z) {
    float t = 0.7978845608028654f * (z + 0.044715f * z * z * z);
    return 0.5f * z * (1.0f + tanhf(t));
}

// ------------------------- kernel 0: rot kernel projection ------------------------
__global__ __launch_bounds__(256) void rotk_kernel(const float* __restrict__ fkb,
                                                   const float* __restrict__ Wr) {
    int po = blockIdx.x * 4 + (threadIdx.x >> 6);
    int c  = threadIdx.x & 63;
    float acc = 0.f;
#pragma unroll
    for (int s = 0; s < 32; s++)
        acc += __ldg(&fkb[po * 32 + s]) * __ldg(&Wr[s * 64 + c]);
    g_rk[po * 64 + c] = acc;
}

// ------------------------- kernel 1: big conv GEMM --------------------------------
// grid (2, 16, 8): m-tile 128 (8 warps x m16n64), o, k-split of 32 n-points.
// A: 4-stage cp.async pipeline in smem. B: tf32(x*Ws) double-buffered in smem.
__global__ __launch_bounds__(256, 2) void conv_kernel(const float* __restrict__ x,
                                                      const float* __restrict__ kb,
                                                      const float* __restrict__ Wsp) {
    extern __shared__ char smem[];
    const uint32_t sbase = smem_u32(smem);
    float*    sA = (float*)smem;                 // [4][128][AST]
    uint32_t* sB = (uint32_t*)(smem + B_OFF);    // [2][64][BST]
    float*    sx = (float*)(smem + SX_OFF);      // [32][64]

    const int tid  = threadIdx.x;
    const int w    = tid >> 5;
    const int lane = tid & 31;
    const int g    = lane >> 2;
    const int tq   = lane & 3;
    const int m0   = blockIdx.x * 128;
    const int o    = blockIdx.y;
    const int ks   = blockIdx.z;
    const int n0   = ks * 32;

    // A prefetch of one tile into stage st (1024 x 16B chunks; 4 per thread)
    auto prefetchA = [&](int t, int st) {
        const int n = n0 + t;
        const uint32_t abase = sbase + st * A_STAGE;
        const float* srcb = kb + (size_t)m0 * 131072 + (size_t)n * 512 + o * 32;
#pragma unroll
        for (int h = 0; h < 4; h++) {
            int q = tid + h * 256;
            int r = q >> 3, j = q & 7;
            cpa16(abase + (uint32_t)(r * AST + j * 4) * 4,
                  srcb + (size_t)r * 131072 + j * 4);
        }
    };

    prefetchA(0, 0); asm volatile("cp.async.commit_group;" ::: "memory");
    prefetchA(1, 1); asm volatile("cp.async.commit_group;" ::: "memory");
    prefetchA(2, 2); asm volatile("cp.async.commit_group;" ::: "memory");

    // x rows for our 32 n-points
    for (int i4 = tid; i4 < 512; i4 += 256) {
        int n_i = i4 >> 4, c4 = i4 & 15;
        ((float4*)sx)[i4] = __ldg((const float4*)(x + (size_t)(n0 + n_i) * 1024 + o * 64 + c4 * 4));
    }

    // B-build assignment: thread -> (c = tid/4, k-range bq0 = (tid%4)*8)
    const int bc = tid >> 2, bq0 = (tid & 3) * 8;
    float ws[8];
#pragma unroll
    for (int i = 0; i < 8; i++) ws[i] = __ldg(&Wsp[(bq0 + i) * 64 + bc]);

    __syncthreads();   // sx visible

    auto buildB = [&](int buf, int t) {
        float xv = sx[t * 64 + bc];
        uint32_t* dst = &sB[buf * (64 * BST) + bc * BST + bq0];
        uint4 u0, u1;
        u0.x = f2tf(xv * ws[0]); u0.y = f2tf(xv * ws[1]);
        u0.z = f2tf(xv * ws[2]); u0.w = f2tf(xv * ws[3]);
        u1.x = f2tf(xv * ws[4]); u1.y = f2tf(xv * ws[5]);
        u1.z = f2tf(xv * ws[6]); u1.w = f2tf(xv * ws[7]);
        *(uint4*)dst       = u0;
        *(uint4*)(dst + 4) = u1;
    };

    buildB(0, 0);

    float acc[8][4];
#pragma unroll
    for (int G = 0; G < 8; G++)
#pragma unroll
        for (int i = 0; i < 4; i++) acc[G][i] = 0.f;

    const int arow0 = (w * 16 + g) * AST + 2 * tq;
    const int arow1 = arow0 + 8 * AST;

    for (int t = 0; t < NT; t++) {
        // tile t's A stage complete (groups: 3 prologue + 1/iter, unconditional commits)
        asm volatile("cp.async.wait_group 2;" ::: "memory");
        __syncthreads();   // A(t), B(t) visible; all reads of overwrite targets done

        if (t + 3 < NT) prefetchA(t + 3, (t + 3) & 3);
        asm volatile("cp.async.commit_group;" ::: "memory");
        if (t + 1 < NT) buildB((t + 1) & 1, t + 1);

        const float*    At = sA + (t & 3) * (128 * AST);
        const uint32_t* BT = sB + (t & 1) * (64 * BST);
#pragma unroll
        for (int j = 0; j < 4; j++) {
            float2 p0 = *(const float2*)&At[arow0 + 8 * j];
            float2 p1 = *(const float2*)&At[arow1 + 8 * j];
            uint32_t a0 = f2tf(p0.x), a2 = f2tf(p0.y);
            uint32_t a1 = f2tf(p1.x), a3 = f2tf(p1.y);
            const int ko = 8 * j + 2 * tq;
#pragma unroll
            for (int G = 0; G < 8; G++) {
                uint2 b = *(const uint2*)&BT[(G * 8 + g) * BST + ko];
                mma8(acc[G], a0, a1, a2, a3, b.x, b.y);
            }
        }
    }

    // epilogue: partials to gmem. D frag: c0=(g,2tq) c1=+1 c2=(g+8,2tq) c3=+1
    {
        float* dst0 = g_h1[ks] + ((size_t)(m0 + w * 16 + g) * 16 + o) * 64 + 2 * tq;
        float* dst1 = dst0 + (size_t)8 * 16 * 64;
#pragma unroll
        for (int G = 0; G < 8; G++) {
            float2 v0 = {acc[G][0], acc[G][1]};
            float2 v1 = {acc[G][2], acc[G][3]};
            *(float2*)(dst0 + G * 8) = v0;
            *(float2*)(dst1 + G * 8) = v1;
        }
    }
}

// ------------------------- kernel 2: partial-sum + fiber conv + LN ----------------
// grid 256 (one m each), 256 threads.
__global__ __launch_bounds__(256) void tailA_kernel(const float* __restrict__ cb,
                                                    const float* __restrict__ lns,
                                                    const float* __restrict__ lnb) {
    __shared__ __align__(16) float hs[1024];   // summed conv output [16 o][64 c]

    const int tid = threadIdx.x;
    const int m   = blockIdx.x;

    // 1) sum KS k-split partials (one float4 per thread)
    {
        float4 a = ((const float4*)g_h1[0])[m * 256 + tid];
#pragma unroll
        for (int q = 1; q < KS; q++) {
            float4 b = ((const float4*)g_h1[q])[m * 256 + tid];
            a.x += b.x; a.y += b.y; a.z += b.z; a.w += b.w;
        }
        ((float4*)hs)[tid] = a;
    }
    __syncthreads();

    // 2) fiber conv over o + bias, LN over c (16 lanes per row)
    {
        const int p  = tid >> 4;
        const int ci = tid & 15;
        const int c0 = ci * 4;
        float hv[4];
#pragma unroll
        for (int j = 0; j < 4; j++) hv[j] = __ldg(&cb[c0 + j]);
#pragma unroll
        for (int oo = 0; oo < 16; oo++) {
            float4 h4 = ((const float4*)hs)[oo * 16 + ci];
            float4 r4 = __ldg((const float4*)&g_rk[(p * 16 + oo) * 64 + c0]);
            hv[0] += h4.x * r4.x; hv[1] += h4.y * r4.y;
            hv[2] += h4.z * r4.z; hv[3] += h4.w * r4.w;
        }
        float s = hv[0] + hv[1] + hv[2] + hv[3];
        s += __shfl_xor_sync(0xffffffffu, s, 1);
        s += __shfl_xor_sync(0xffffffffu, s, 2);
        s += __shfl_xor_sync(0xffffffffu, s, 4);
        s += __shfl_xor_sync(0xffffffffu, s, 8);
        float mu = s * (1.f / 64.f);
        float d[4], ss = 0.f;
#pragma unroll
        for (int j = 0; j < 4; j++) { d[j] = hv[j] - mu; ss += d[j] * d[j]; }
        ss += __shfl_xor_sync(0xffffffffu, ss, 1);
        ss += __shfl_xor_sync(0xffffffffu, ss, 2);
        ss += __shfl_xor_sync(0xffffffffu, ss, 4);
        ss += __shfl_xor_sync(0xffffffffu, ss, 8);
        float rs = rsqrtf(ss * (1.f / 64.f) + 1e-6f);
        float4 ov;
        ov.x = d[0] * rs * __ldg(&lns[c0 + 0]) + __ldg(&lnb[c0 + 0]);
        ov.y = d[1] * rs * __ldg(&lns[c0 + 1]) + __ldg(&lnb[c0 + 1]);
        ov.z = d[2] * rs * __ldg(&lns[c0 + 2]) + __ldg(&lnb[c0 + 2]);
        ov.w = d[3] * rs * __ldg(&lns[c0 + 3]) + __ldg(&lnb[c0 + 3]);
        *(float4*)&g_v[(m * 16 + p) * 64 + c0] = ov;
    }
}

// ------------------------- kernel 3: MLP + residual -------------------------------
// grid 512 (8 rows each), 256 threads.
__global__ __launch_bounds__(256) void tailB_kernel(const float* __restrict__ x,
                                                    const float* __restrict__ W1,
                                                    const float* __restrict__ b1,
                                                    const float* __restrict__ W2,
                                                    const float* __restrict__ b2,
                                                    float* __restrict__ out) {
    __shared__ __align__(16) float v8[8 * 64];
    __shared__ __align__(16) float u8[8 * 260];

    const int tid = threadIdx.x;
    const int r0  = blockIdx.x * 8;   // first global row (m*16+p)

    ((float2*)v8)[tid] = ((const float2*)(g_v + (size_t)r0 * 64))[tid];
    __syncthreads();

    // GEMM1 (64 -> 256) + gelu
    {
        const int r  = tid >> 5;
        const int j0 = (tid & 31) * 8;
        float acc[8];
#pragma unroll
        for (int j = 0; j < 8; j++) acc[j] = 0.f;
        for (int c = 0; c < 64; c++) {
            float vv = v8[r * 64 + c];
            float4 wa = __ldg((const float4*)&W1[c * 256 + j0]);
            float4 wb = __ldg((const float4*)&W1[c * 256 + j0 + 4]);
            acc[0] += vv * wa.x; acc[1] += vv * wa.y;
            acc[2] += vv * wa.z; acc[3] += vv * wa.w;
            acc[4] += vv * wb.x; acc[5] += vv * wb.y;
            acc[6] += vv * wb.z; acc[7] += vv * wb.w;
        }
        float4 s0, s1;
        s0.x = gelu_f(acc[0] + __ldg(&b1[j0 + 0]));
        s0.y = gelu_f(acc[1] + __ldg(&b1[j0 + 1]));
        s0.z = gelu_f(acc[2] + __ldg(&b1[j0 + 2]));
        s0.w = gelu_f(acc[3] + __ldg(&b1[j0 + 3]));
        s1.x = gelu_f(acc[4] + __ldg(&b1[j0 + 4]));
        s1.y = gelu_f(acc[5] + __ldg(&b1[j0 + 5]));
        s1.z = gelu_f(acc[6] + __ldg(&b1[j0 + 6]));
        s1.w = gelu_f(acc[7] + __ldg(&b1[j0 + 7]));
        *(float4*)&u8[r * 260 + j0]     = s0;
        *(float4*)&u8[r * 260 + j0 + 4] = s1;
    }
    __syncthreads();

    // GEMM2 (256 -> 64) + bias + residual
    {
        const int r  = tid >> 5;
        const int c0 = (tid & 31) * 2;
        float a0 = 0.f, a1 = 0.f;
        for (int jj = 0; jj < 256; jj++) {
            float uu = u8[r * 260 + jj];
            float2 wv = __ldg((const float2*)&W2[jj * 64 + c0]);
            a0 += uu * wv.x;
            a1 += uu * wv.y;
        }
        const int grow = r0 + r;
        float2 bb = __ldg((const float2*)&b2[c0]);
        float2 xr = __ldg((const float2*)&x[(size_t)grow * 64 + c0]);
        float2 rv;
        rv.x = a0 + bb.x + xr.x;
        rv.y = a1 + bb.y + xr.y;
        *(float2*)&out[(size_t)grow * 64 + c0] = rv;
    }
}

// ------------------------- launch ------------------------------------------------
extern "C" void kernel_launch(void* const* d_in, const int* in_sizes, int n_in,
                              void* d_out, int out_size) {
    const float* x   = (const float*)d_in[0];
    const float* kb  = (const float*)d_in[1];
    const float* fkb = (const float*)d_in[2];
    const float* Wsp = (const float*)d_in[3];
    const float* Wr  = (const float*)d_in[4];
    const float* cb  = (const float*)d_in[5];
    const float* lns = (const float*)d_in[6];
    const float* lnb = (const float*)d_in[7];
    const float* W1  = (const float*)d_in[8];
    const float* b1  = (const float*)d_in[9];
    const float* W2  = (const float*)d_in[10];
    const float* b2  = (const float*)d_in[11];
    float* out = (float*)d_out;

    cudaFuncSetAttribute(conv_kernel, cudaFuncAttributeMaxDynamicSharedMemorySize, SMEMSZ);

    rotk_kernel<<<64, 256>>>(fkb, Wr);
    conv_kernel<<<dim3(2, 16, 8), 256, SMEMSZ>>>(x, kb, Wsp);
    tailA_kernel<<<256, 256>>>(cb, lns, lnb);
    tailB_kernel<<<512, 256>>>(x, W1, b1, W2, b2, out);
}

// round 6
// speedup vs baseline: 1.9189x; 1.2686x over previous
#include <cuda_runtime.h>
#include <cstdint>
#include <math.h>

// Problem: B=1, N=256, O=16, C=64, BASIS=32, WIDEN=4
// h[m,o,c] = sum_{n,s} kb[m,n,o,s] * x[n,o,c] * Ws[s,c]   (tf32 mma.sync)
// then fiber conv over o with rk = fkb@Wr, +bias, LN, MLP(gelu), +x residual.

#define KS 8
#define NT 32
#define AST 40                    // A smem row stride (words): conflict-free LDS.64
#define BST 40                    // B smem row stride (words)
#define A_STAGE (128 * AST * 4)   // 20480 B per A stage
#define B_BUF   (64 * BST * 4)    // 10240 B per B buffer
#define B_OFF   (4 * A_STAGE)     // 81920
#define SX_OFF  (B_OFF + 2 * B_BUF)     // 102400
#define SMEMSZ  (SX_OFF + 32 * 64 * 4)  // 110592

__device__ float g_rk[16 * 16 * 64];
__device__ float g_h1[KS][256 * 16 * 64];

// ------------------------- helpers ------------------------------------------------
__device__ __forceinline__ uint32_t f2tf(float f) {
    uint32_t u;
    asm("cvt.rna.tf32.f32 %0, %1;" : "=r"(u) : "f"(f));
    return u;
}
__device__ __forceinline__ uint32_t smem_u32(const void* p) {
    uint32_t a;
    asm("{ .reg .u64 t; cvta.to.shared.u64 t, %1; cvt.u32.u64 %0, t; }" : "=r"(a) : "l"(p));
    return a;
}
__device__ __forceinline__ void cpa16(uint32_t smemdst, const void* gsrc) {
    asm volatile("cp.async.cg.shared.global [%0], [%1], 16;" :: "r"(smemdst), "l"(gsrc));
}
__device__ __forceinline__ void mma8(float* acc,
                                     uint32_t a0, uint32_t a1, uint32_t a2, uint32_t a3,
                                     uint32_t b0, uint32_t b1) {
    asm volatile(
        "mma.sync.aligned.m16n8k8.row.col.f32.tf32.tf32.f32 "
        "{%0,%1,%2,%3}, {%4,%5,%6,%7}, {%8,%9}, {%0,%1,%2,%3};"
        : "+f"(acc[0]), "+f"(acc[1]), "+f"(acc[2]), "+f"(acc[3])
        : "r"(a0), "r"(a1), "r"(a2), "r"(a3), "r"(b0), "r"(b1));
}
__device__ __forceinline__ float gelu_f(float z) {
    float t = 0.7978845608028654f * (z + 0.044715f * z * z * z);
    return 0.5f * z * (1.0f + tanhf(t));
}

// ------------------------- kernel 0: rot kernel projection ------------------------
__global__ __launch_bounds__(256) void rotk_kernel(const float* __restrict__ fkb,
                                                   const float* __restrict__ Wr) {
    int po = blockIdx.x * 4 + (threadIdx.x >> 6);
    int c  = threadIdx.x & 63;
    float acc = 0.f;
#pragma unroll
    for (int s = 0; s < 32; s++)
        acc += __ldg(&fkb[po * 32 + s]) * __ldg(&Wr[s * 64 + c]);
    g_rk[po * 64 + c] = acc;
}

// ------------------------- kernel 1: big conv GEMM --------------------------------
// grid (2, 16, 8): m-tile 128 (8 warps x m16n64), o, k-split of 32 n-points.
// A: 4-stage cp.async pipeline in smem. B: tf32(x*Ws) double-buffered in smem.
__global__ __launch_bounds__(256, 2) void conv_kernel(const float* __restrict__ x,
                                                      const float* __restrict__ kb,
                                                      const float* __restrict__ Wsp) {
    extern __shared__ char smem[];
    const uint32_t sbase = smem_u32(smem);
    float*    sA = (float*)smem;                 // [4][128][AST]
    uint32_t* sB = (uint32_t*)(smem + B_OFF);    // [2][64][BST]
    float*    sx = (float*)(smem + SX_OFF);      // [32][64]

    const int tid  = threadIdx.x;
    const int w    = tid >> 5;
    const int lane = tid & 31;
    const int g    = lane >> 2;
    const int tq   = lane & 3;
    const int m0   = blockIdx.x * 128;
    const int o    = blockIdx.y;
    const int ks   = blockIdx.z;
    const int n0   = ks * 32;

    auto prefetchA = [&](int t, int st) {
        const int n = n0 + t;
        const uint32_t abase = sbase + st * A_STAGE;
        const float* srcb = kb + (size_t)m0 * 131072 + (size_t)n * 512 + o * 32;
#pragma unroll
        for (int h = 0; h < 4; h++) {
            int q = tid + h * 256;
            int r = q >> 3, j = q & 7;
            cpa16(abase + (uint32_t)(r * AST + j * 4) * 4,
                  srcb + (size_t)r * 131072 + j * 4);
        }
    };

    prefetchA(0, 0); asm volatile("cp.async.commit_group;" ::: "memory");
    prefetchA(1, 1); asm volatile("cp.async.commit_group;" ::: "memory");
    prefetchA(2, 2); asm volatile("cp.async.commit_group;" ::: "memory");

    for (int i4 = tid; i4 < 512; i4 += 256) {
        int n_i = i4 >> 4, c4 = i4 & 15;
        ((float4*)sx)[i4] = __ldg((const float4*)(x + (size_t)(n0 + n_i) * 1024 + o * 64 + c4 * 4));
    }

    const int bc = tid >> 2, bq0 = (tid & 3) * 8;
    float ws[8];
#pragma unroll
    for (int i = 0; i < 8; i++) ws[i] = __ldg(&Wsp[(bq0 + i) * 64 + bc]);

    __syncthreads();   // sx visible

    auto buildB = [&](int buf, int t) {
        float xv = sx[t * 64 + bc];
        uint32_t* dst = &sB[buf * (64 * BST) + bc * BST + bq0];
        uint4 u0, u1;
        u0.x = f2tf(xv * ws[0]); u0.y = f2tf(xv * ws[1]);
        u0.z = f2tf(xv * ws[2]); u0.w = f2tf(xv * ws[3]);
        u1.x = f2tf(xv * ws[4]); u1.y = f2tf(xv * ws[5]);
        u1.z = f2tf(xv * ws[6]); u1.w = f2tf(xv * ws[7]);
        *(uint4*)dst       = u0;
        *(uint4*)(dst + 4) = u1;
    };

    buildB(0, 0);

    float acc[8][4];
#pragma unroll
    for (int G = 0; G < 8; G++)
#pragma unroll
        for (int i = 0; i < 4; i++) acc[G][i] = 0.f;

    const int arow0 = (w * 16 + g) * AST + 2 * tq;
    const int arow1 = arow0 + 8 * AST;

    for (int t = 0; t < NT; t++) {
        asm volatile("cp.async.wait_group 2;" ::: "memory");
        __syncthreads();   // A(t), B(t) visible; all reads of overwrite targets done

        if (t + 3 < NT) prefetchA(t + 3, (t + 3) & 3);
        asm volatile("cp.async.commit_group;" ::: "memory");
        if (t + 1 < NT) buildB((t + 1) & 1, t + 1);

        const float*    At = sA + (t & 3) * (128 * AST);
        const uint32_t* BT = sB + (t & 1) * (64 * BST);
#pragma unroll
        for (int j = 0; j < 4; j++) {
            float2 p0 = *(const float2*)&At[arow0 + 8 * j];
            float2 p1 = *(const float2*)&At[arow1 + 8 * j];
            uint32_t a0 = f2tf(p0.x), a2 = f2tf(p0.y);
            uint32_t a1 = f2tf(p1.x), a3 = f2tf(p1.y);
            const int ko = 8 * j + 2 * tq;
#pragma unroll
            for (int G = 0; G < 8; G++) {
                uint2 b = *(const uint2*)&BT[(G * 8 + g) * BST + ko];
                mma8(acc[G], a0, a1, a2, a3, b.x, b.y);
            }
        }
    }

    {
        float* dst0 = g_h1[ks] + ((size_t)(m0 + w * 16 + g) * 16 + o) * 64 + 2 * tq;
        float* dst1 = dst0 + (size_t)8 * 16 * 64;
#pragma unroll
        for (int G = 0; G < 8; G++) {
            float2 v0 = {acc[G][0], acc[G][1]};
            float2 v1 = {acc[G][2], acc[G][3]};
            *(float2*)(dst0 + G * 8) = v0;
            *(float2*)(dst1 + G * 8) = v1;
        }
    }
}

// ------------------------- kernel 2: fused tail -----------------------------------
// grid 256 (one m each), 256 threads.
// partial-sum + fiber conv + LN + MLP (register-blocked) + residual.
__global__ __launch_bounds__(256) void tail_kernel(const float* __restrict__ x,
                                                   const float* __restrict__ cb,
                                                   const float* __restrict__ lns,
                                                   const float* __restrict__ lnb,
                                                   const float* __restrict__ W1,
                                                   const float* __restrict__ b1,
                                                   const float* __restrict__ W2,
                                                   const float* __restrict__ b2,
                                                   float* __restrict__ out) {
    __shared__ __align__(16) float hs[1024];        // summed conv [16 o][64 c]
    __shared__ __align__(16) float v[1024];         // post-LN [16 p][64 c]
    __shared__ __align__(16) float u[16 * 260];     // MLP hidden (padded)
    __shared__ __align__(16) float pp[4][1024];     // GEMM2 partials [jjq][p*64+c]

    const int tid = threadIdx.x;
    const int m   = blockIdx.x;

    // 1) sum KS k-split partials (one float4 per thread)
    {
        float4 a = ((const float4*)g_h1[0])[m * 256 + tid];
#pragma unroll
        for (int q = 1; q < KS; q++) {
            float4 b = ((const float4*)g_h1[q])[m * 256 + tid];
            a.x += b.x; a.y += b.y; a.z += b.z; a.w += b.w;
        }
        ((float4*)hs)[tid] = a;
    }
    __syncthreads();

    // 2) fiber conv over o + bias, LN over c (16 lanes per row)
    {
        const int p  = tid >> 4;
        const int ci = tid & 15;
        const int c0 = ci * 4;
        float hv[4];
#pragma unroll
        for (int j = 0; j < 4; j++) hv[j] = __ldg(&cb[c0 + j]);
#pragma unroll
        for (int oo = 0; oo < 16; oo++) {
            float4 h4 = ((const float4*)hs)[oo * 16 + ci];
            float4 r4 = __ldg((const float4*)&g_rk[(p * 16 + oo) * 64 + c0]);
            hv[0] += h4.x * r4.x; hv[1] += h4.y * r4.y;
            hv[2] += h4.z * r4.z; hv[3] += h4.w * r4.w;
        }
        float s = hv[0] + hv[1] + hv[2] + hv[3];
        s += __shfl_xor_sync(0xffffffffu, s, 1);
        s += __shfl_xor_sync(0xffffffffu, s, 2);
        s += __shfl_xor_sync(0xffffffffu, s, 4);
        s += __shfl_xor_sync(0xffffffffu, s, 8);
        float mu = s * (1.f / 64.f);
        float d[4], ss = 0.f;
#pragma unroll
        for (int j = 0; j < 4; j++) { d[j] = hv[j] - mu; ss += d[j] * d[j]; }
        ss += __shfl_xor_sync(0xffffffffu, ss, 1);
        ss += __shfl_xor_sync(0xffffffffu, ss, 2);
        ss += __shfl_xor_sync(0xffffffffu, ss, 4);
        ss += __shfl_xor_sync(0xffffffffu, ss, 8);
        float rs = rsqrtf(ss * (1.f / 64.f) + 1e-6f);
        float4 ov;
        ov.x = d[0] * rs * __ldg(&lns[c0 + 0]) + __ldg(&lnb[c0 + 0]);
        ov.y = d[1] * rs * __ldg(&lns[c0 + 1]) + __ldg(&lnb[c0 + 1]);
        ov.z = d[2] * rs * __ldg(&lns[c0 + 2]) + __ldg(&lnb[c0 + 2]);
        ov.w = d[3] * rs * __ldg(&lns[c0 + 3]) + __ldg(&lnb[c0 + 3]);
        *(float4*)&v[p * 64 + c0] = ov;
    }
    __syncthreads();

    // 3) GEMM1 (16x64 @ 64x256) + gelu, register-blocked 4 rows x 4 cols
    {
        const int r0 = (tid & 3) * 4;        // 4 rows
        const int j0 = (tid >> 2) * 4;       // 4 cols (0..255)
        float acc[4][4];
#pragma unroll
        for (int i = 0; i < 4; i++)
#pragma unroll
            for (int j = 0; j < 4; j++) acc[i][j] = 0.f;
        for (int c = 0; c < 64; c++) {
            float4 wv = __ldg((const float4*)&W1[c * 256 + j0]);
            float vr[4];
#pragma unroll
            for (int i = 0; i < 4; i++) vr[i] = v[(r0 + i) * 64 + c];
#pragma unroll
            for (int i = 0; i < 4; i++) {
                acc[i][0] += vr[i] * wv.x; acc[i][1] += vr[i] * wv.y;
                acc[i][2] += vr[i] * wv.z; acc[i][3] += vr[i] * wv.w;
            }
        }
        float4 bv = __ldg((const float4*)&b1[j0]);
#pragma unroll
        for (int i = 0; i < 4; i++) {
            float4 s;
            s.x = gelu_f(acc[i][0] + bv.x);
            s.y = gelu_f(acc[i][1] + bv.y);
            s.z = gelu_f(acc[i][2] + bv.z);
            s.w = gelu_f(acc[i][3] + bv.w);
            *(float4*)&u[(r0 + i) * 260 + j0] = s;
        }
    }
    __syncthreads();

    // 4) GEMM2 (16x256 @ 256x64), 4-way k-split, 4 rows x 4 cols per thread
    {
        const int jjq = tid >> 6;            // k-split quarter (64 jj each)
        const int cg  = (tid >> 2) & 15;     // col group
        const int r0  = (tid & 3) * 4;       // 4 rows
        const int c0  = cg * 4;              // 4 cols
        float acc[4][4];
#pragma unroll
        for (int i = 0; i < 4; i++)
#pragma unroll
            for (int j = 0; j < 4; j++) acc[i][j] = 0.f;
        const int jb = jjq * 64;
        for (int jj = jb; jj < jb + 64; jj++) {
            float4 wv = __ldg((const float4*)&W2[jj * 64 + c0]);
            float ur[4];
#pragma unroll
            for (int i = 0; i < 4; i++) ur[i] = u[(r0 + i) * 260 + jj];
#pragma unroll
            for (int i = 0; i < 4; i++) {
                acc[i][0] += ur[i] * wv.x; acc[i][1] += ur[i] * wv.y;
                acc[i][2] += ur[i] * wv.z; acc[i][3] += ur[i] * wv.w;
            }
        }
#pragma unroll
        for (int i = 0; i < 4; i++) {
            float4 s = {acc[i][0], acc[i][1], acc[i][2], acc[i][3]};
            *(float4*)&pp[jjq][(r0 + i) * 64 + c0] = s;
        }
    }
    __syncthreads();

    // 5) reduce k-split partials + bias + residual, one float4 per thread
    {
        float4 a = ((const float4*)pp[0])[tid];
        float4 b = ((const float4*)pp[1])[tid];
        float4 c = ((const float4*)pp[2])[tid];
        float4 d = ((const float4*)pp[3])[tid];
        float4 bb = __ldg((const float4*)&b2[(tid & 15) * 4]);
        float4 xr = __ldg(((const float4*)x) + m * 256 + tid);
        float4 r;
        r.x = a.x + b.x + c.x + d.x + bb.x + xr.x;
        r.y = a.y + b.y + c.y + d.y + bb.y + xr.y;
        r.z = a.z + b.z + c.z + d.z + bb.z + xr.z;
        r.w = a.w + b.w + c.w + d.w + bb.w + xr.w;
        ((float4*)out)[m * 256 + tid] = r;
    }
}

// ------------------------- launch ------------------------------------------------
extern "C" void kernel_launch(void* const* d_in, const int* in_sizes, int n_in,
                              void* d_out, int out_size) {
    const float* x   = (const float*)d_in[0];
    const float* kb  = (const float*)d_in[1];
    const float* fkb = (const float*)d_in[2];
    const float* Wsp = (const float*)d_in[3];
    const float* Wr  = (const float*)d_in[4];
    const float* cb  = (const float*)d_in[5];
    const float* lns = (const float*)d_in[6];
    const float* lnb = (const float*)d_in[7];
    const float* W1  = (const float*)d_in[8];
    const float* b1  = (const float*)d_in[9];
    const float* W2  = (const float*)d_in[10];
    const float* b2  = (const float*)d_in[11];
    float* out = (float*)d_out;

    cudaFuncSetAttribute(conv_kernel, cudaFuncAttributeMaxDynamicSharedMemorySize, SMEMSZ);

    rotk_kernel<<<64, 256>>>(fkb, Wr);
    conv_kernel<<<dim3(2, 16, 8), 256, SMEMSZ>>>(x, kb, Wsp);
    tail_kernel<<<256, 256>>>(x, cb, lns, lnb, W1, b1, W2, b2, out);
}